// round 2
// baseline (speedup 1.0000x reference)
#include <cuda_runtime.h>
#include <cstdint>

#define NMAX 50000
#define RR 3
#define GGR 64

// ---------------- scratch (device globals; no allocation) ----------------
__device__ float g_xr   [RR*NMAX*64];
__device__ float g_beta [RR*NMAX*64];
__device__ float g_gamma[RR*NMAX*64];
__device__ float g_xs   [NMAX*64];
__device__ float g_fsb  [NMAX*64];
__device__ float g_fsg  [NMAX*64];
__device__ float g_xp   [NMAX*64];
__device__ float g_asrc [NMAX];
__device__ float g_adst [NMAX];
__device__ float g_agg  [NMAX*64];
__device__ float g_gacc [NMAX*64];
__device__ float g_den  [NMAX];
__device__ unsigned g_mkey[NMAX];
__device__ int   g_cnt  [NMAX*RR];
__device__ float g_feats[NMAX*128];
__device__ float g_pmax [GGR*128];
__device__ float g_pmean[GGR*128];
__device__ float g_hidden[GGR*64];

// ---------------- helpers ----------------
__device__ __forceinline__ uint64_t pack2(float a, float b){
    uint64_t r; asm("mov.b64 %0,{%1,%2};" : "=l"(r) : "f"(a), "f"(b)); return r;
}
__device__ __forceinline__ void fma2(uint64_t &d, uint64_t a, uint64_t b){
    asm("fma.rn.f32x2 %0,%1,%2,%0;" : "+l"(d) : "l"(a), "l"(b));
}
__device__ __forceinline__ unsigned fkey(float f){
    unsigned u = __float_as_uint(f);
    return (u & 0x80000000u) ? ~u : (u | 0x80000000u);
}
__device__ __forceinline__ float funkey(unsigned k){
    return __uint_as_float((k & 0x80000000u) ? (k ^ 0x80000000u) : ~k);
}

// ---------------- init ----------------
__global__ void kinit(int n){
    int i = blockIdx.x*blockDim.x + threadIdx.x;
    if (i < n*64){ g_agg[i] = 0.f; g_gacc[i] = 0.f; }
    if (i < n)   { g_den[i] = 0.f; g_mkey[i] = 0u; }
    if (i < n*RR) g_cnt[i] = 0;
}

// ---------------- K1: fused node-dense GEMMs ----------------
__device__ __forceinline__ void tile64(
    const float* __restrict__ Wg, int ldw, int jof,
    const float* __restrict__ bias,
    float* __restrict__ outArr,
    float* Ws, const float* Xs, int tid, int node, int n)
{
    __syncthreads();
    #pragma unroll
    for (int k = tid; k < 4096; k += 128)
        Ws[k] = Wg[(k>>6)*ldw + jof + (k&63)];
    __syncthreads();

    uint64_t acc[32];
    if (bias){
        #pragma unroll
        for (int j = 0; j < 32; j++) acc[j] = pack2(bias[jof+2*j], bias[jof+2*j+1]);
    } else {
        #pragma unroll
        for (int j = 0; j < 32; j++) acc[j] = 0ull;
    }
    for (int d = 0; d < 64; d++){
        float xv = Xs[d*128 + tid];
        uint64_t x2 = pack2(xv, xv);
        const ulonglong2* wr = (const ulonglong2*)(Ws + d*64);
        #pragma unroll
        for (int j = 0; j < 16; j++){
            ulonglong2 w = wr[j];
            fma2(acc[2*j],   x2, w.x);
            fma2(acc[2*j+1], x2, w.y);
        }
    }
    if (node < n){
        ulonglong2* o = (ulonglong2*)(outArr + (size_t)node*64);
        #pragma unroll
        for (int j = 0; j < 16; j++) o[j] = make_ulonglong2(acc[2*j], acc[2*j+1]);
    }
}

__global__ __launch_bounds__(128) void k1(
    const float* __restrict__ x,
    const float* __restrict__ flW, const float* __restrict__ ffW, const float* __restrict__ ffb,
    const float* __restrict__ skW, const float* __restrict__ sfW, const float* __restrict__ sfb,
    const float* __restrict__ gatW, int n)
{
    extern __shared__ float sm[];
    float* Ws = sm;          // 4096 floats
    float* Xs = sm + 4096;   // 64*128 floats
    int tid = threadIdx.x;
    int node = blockIdx.x*128 + tid;
    int nc = node < n ? node : n-1;

    const float4* xr4 = (const float4*)(x + (size_t)nc*64);
    #pragma unroll
    for (int q = 0; q < 16; q++){
        float4 v = xr4[q];
        Xs[(4*q+0)*128 + tid] = v.x;
        Xs[(4*q+1)*128 + tid] = v.y;
        Xs[(4*q+2)*128 + tid] = v.z;
        Xs[(4*q+3)*128 + tid] = v.w;
    }

    tile64(skW, 64, 0,  (const float*)nullptr, g_xs,  Ws, Xs, tid, node, n);
    tile64(sfW, 128, 0,  sfb, g_fsb, Ws, Xs, tid, node, n);
    tile64(sfW, 128, 64, sfb, g_fsg, Ws, Xs, tid, node, n);
    for (int r = 0; r < RR; r++){
        tile64(flW + (size_t)r*64*64,  64, 0,  (const float*)nullptr,
               g_xr + (size_t)r*n*64, Ws, Xs, tid, node, n);
        tile64(ffW + (size_t)r*64*128, 128, 0,  ffb + r*128,
               g_beta + (size_t)r*n*64, Ws, Xs, tid, node, n);
        tile64(ffW + (size_t)r*64*128, 128, 64, ffb + r*128,
               g_gamma + (size_t)r*n*64, Ws, Xs, tid, node, n);
    }
    tile64(gatW, 64, 0, (const float*)nullptr, g_xp, Ws, Xs, tid, node, n);
}

// ---------------- K1b: attention scores ----------------
__global__ void k1b(const float* __restrict__ atS, const float* __restrict__ atD, int n){
    int w = (blockIdx.x*blockDim.x + threadIdx.x) >> 5;
    int lane = threadIdx.x & 31;
    if (w >= n) return;
    float2 v = ((const float2*)(g_xp + (size_t)w*64))[lane];
    float a = v.x*atS[2*lane] + v.y*atS[2*lane+1];
    float b = v.x*atD[2*lane] + v.y*atD[2*lane+1];
    #pragma unroll
    for (int o = 16; o; o >>= 1){
        a += __shfl_down_sync(0xffffffffu, a, o);
        b += __shfl_down_sync(0xffffffffu, b, o);
    }
    if (lane == 0){ g_asrc[w] = a; g_adst[w] = b; }
}

// ---------------- K2: per-(dst,type) counts + segment max ----------------
__global__ void k2(const int* __restrict__ src, const int* __restrict__ dst,
                   const int* __restrict__ et, int E, int n){
    int i = blockIdx.x*blockDim.x + threadIdx.x;
    if (i < E){
        int s = src[i], d = dst[i], t = et[i];
        atomicAdd(&g_cnt[d*RR + t], 1);
        float ev = g_asrc[s] + g_adst[d];
        ev = ev < 0.f ? 0.2f*ev : ev;
        atomicMax(&g_mkey[d], fkey(ev));
    } else if (i < E + n){
        int v = i - E;
        float ev = g_asrc[v] + g_adst[v];
        ev = ev < 0.f ? 0.2f*ev : ev;
        atomicMax(&g_mkey[v], fkey(ev));
    }
}

// ---------------- K3: FiLM edge messages ----------------
__global__ void k3(const int* __restrict__ src, const int* __restrict__ dst,
                   const int* __restrict__ et, int E, int n){
    int w = (blockIdx.x*blockDim.x + threadIdx.x) >> 5;
    int lane = threadIdx.x & 31;
    if (w >= E) return;
    int s = src[w], d = dst[w], t = et[w];
    int c = g_cnt[d*RR + t];
    float invden = 1.f / (float)(c > 0 ? c : 1);
    size_t so = ((size_t)t*n + s)*64;
    size_t dofs = ((size_t)t*n + d)*64;
    float2 xv = ((const float2*)(g_xr    + so  ))[lane];
    float2 gv = ((const float2*)(g_gamma + dofs))[lane];
    float2 bv = ((const float2*)(g_beta  + dofs))[lane];
    float mx = fmaxf(fmaf(gv.x, xv.x, bv.x), 0.f) * invden;
    float my = fmaxf(fmaf(gv.y, xv.y, bv.y), 0.f) * invden;
    float* a = g_agg + (size_t)d*64 + lane*2;
    atomicAdd(a,     mx);
    atomicAdd(a + 1, my);
}

// ---------------- K4: GAT aggregate (unnormalized softmax) ----------------
__global__ void k4(const int* __restrict__ src, const int* __restrict__ dst, int E, int n){
    int w = (blockIdx.x*blockDim.x + threadIdx.x) >> 5;
    int lane = threadIdx.x & 31;
    if (w >= E + n) return;
    int s, d;
    if (w < E){ s = src[w]; d = dst[w]; } else { s = d = w - E; }
    float ev = g_asrc[s] + g_adst[d];
    ev = ev < 0.f ? 0.2f*ev : ev;
    float mv = funkey(g_mkey[d]);
    float alpha = __expf(ev - mv);
    float2 xv = ((const float2*)(g_xp + (size_t)s*64))[lane];
    float* a = g_gacc + (size_t)d*64 + lane*2;
    atomicAdd(a,     alpha*xv.x);
    atomicAdd(a + 1, alpha*xv.y);
    if (lane == 0) atomicAdd(&g_den[d], alpha);
}

// ---------------- K5: finalize per-node features ----------------
__global__ void k5(const float* __restrict__ gatb, int n){
    int w = (blockIdx.x*blockDim.x + threadIdx.x) >> 5;
    int lane = threadIdx.x & 31;
    if (w >= n) return;
    size_t o = (size_t)w*64 + lane*2;
    float2 xs = *(const float2*)(g_xs  + o);
    float2 fb = *(const float2*)(g_fsb + o);
    float2 fg = *(const float2*)(g_fsg + o);
    float2 ag = *(const float2*)(g_agg + o);
    float o1x = fmaxf(fmaxf(fmaf(fg.x, xs.x, fb.x), 0.f) + ag.x, 0.f);
    float o1y = fmaxf(fmaxf(fmaf(fg.y, xs.y, fb.y), 0.f) + ag.y, 0.f);
    float invd = 1.f / g_den[w];
    float2 gc = *(const float2*)(g_gacc + o);
    float o2x = fmaxf(fmaf(gc.x, invd, gatb[2*lane  ]), 0.f);
    float o2y = fmaxf(fmaf(gc.y, invd, gatb[2*lane+1]), 0.f);
    float* f = g_feats + (size_t)w*128;
    *(float2*)(f + 2*lane)      = make_float2(o1x, o1y);
    *(float2*)(f + 64 + 2*lane) = make_float2(o2x, o2y);
}

// ---------------- pooling: block per graph, no atomics ----------------
__global__ void kpool(const int* __restrict__ gb, int n){
    int g = blockIdx.x, c = threadIdx.x; // 128 threads
    int lo = 0, hi = n;
    while (lo < hi){ int m = (lo+hi)>>1; if (gb[m] < g) lo = m+1; else hi = m; }
    int start = lo; hi = n;
    while (lo < hi){ int m = (lo+hi)>>1; if (gb[m] < g+1) lo = m+1; else hi = m; }
    int end = lo;
    float mx = 0.f, sm = 0.f;
    for (int i = start; i < end; i++){
        float v = g_feats[(size_t)i*128 + c];
        mx = fmaxf(mx, v); sm += v;
    }
    int cnt = end - start;
    g_pmax[g*128 + c]  = mx;
    g_pmean[g*128 + c] = sm / (float)(cnt > 0 ? cnt : 1);
}

// ---------------- MLP hidden ----------------
__global__ void k6a(const float* __restrict__ linW, const float* __restrict__ linb){
    int idx = blockIdx.x*blockDim.x + threadIdx.x;
    if (idx >= GGR*64) return;
    int g = idx >> 6, j = idx & 63;
    float s = linb[j];
    #pragma unroll 4
    for (int k = 0; k < 128; k++) s = fmaf(g_pmax[g*128 + k],  linW[k*64 + j], s);
    #pragma unroll 4
    for (int k = 0; k < 128; k++) s = fmaf(g_pmean[g*128 + k], linW[(128+k)*64 + j], s);
    g_hidden[idx] = fmaxf(s, 0.f);
}

// ---------------- logits + log_softmax ----------------
__global__ void k6b(const float* __restrict__ fcW, const float* __restrict__ fcb,
                    float* __restrict__ out){
    int g = threadIdx.x;
    if (g >= GGR) return;
    float l[10];
    #pragma unroll
    for (int c = 0; c < 10; c++) l[c] = fcb[c];
    for (int j = 0; j < 64; j++){
        float h = g_hidden[g*64 + j];
        #pragma unroll
        for (int c = 0; c < 10; c++) l[c] = fmaf(h, fcW[j*10 + c], l[c]);
    }
    float mx = l[0];
    #pragma unroll
    for (int c = 1; c < 10; c++) mx = fmaxf(mx, l[c]);
    float se = 0.f;
    #pragma unroll
    for (int c = 0; c < 10; c++) se += expf(l[c] - mx);
    float lse = mx + logf(se);
    #pragma unroll
    for (int c = 0; c < 10; c++) out[g*10 + c] = l[c] - lse;
}

// ---------------- launch ----------------
extern "C" void kernel_launch(void* const* d_in, const int* in_sizes, int n_in,
                              void* d_out, int out_size){
    const float* x    = (const float*)d_in[0];
    const int*   ei   = (const int*)  d_in[1];
    const int*   et   = (const int*)  d_in[2];
    const int*   gb   = (const int*)  d_in[3];
    const float* flW  = (const float*)d_in[4];
    const float* ffW  = (const float*)d_in[5];
    const float* ffb  = (const float*)d_in[6];
    const float* skW  = (const float*)d_in[7];
    const float* sfW  = (const float*)d_in[8];
    const float* sfb  = (const float*)d_in[9];
    const float* gatW = (const float*)d_in[10];
    const float* atS  = (const float*)d_in[11];
    const float* atD  = (const float*)d_in[12];
    const float* gatb = (const float*)d_in[13];
    const float* linW = (const float*)d_in[14];
    const float* linb = (const float*)d_in[15];
    const float* fcW  = (const float*)d_in[16];
    const float* fcb  = (const float*)d_in[17];

    int n = in_sizes[0] / 64;
    int E = in_sizes[1] / 2;
    const int* src = ei;
    const int* dst = ei + E;

    kinit<<<(n*64 + 255)/256, 256>>>(n);
    k1<<<(n + 127)/128, 128, 49152>>>(x, flW, ffW, ffb, skW, sfW, sfb, gatW, n);
    k1b<<<(n + 7)/8, 256>>>(atS, atD, n);
    k2<<<(E + n + 255)/256, 256>>>(src, dst, et, E, n);
    k3<<<(E + 7)/8, 256>>>(src, dst, et, E, n);
    k4<<<(E + n + 7)/8, 256>>>(src, dst, E, n);
    k5<<<(n + 7)/8, 256>>>(gatb, n);
    kpool<<<GGR, 128>>>(gb, n);
    k6a<<<(GGR*64 + 127)/128, 128>>>(linW, linb);
    k6b<<<1, 64>>>(fcW, fcb, (float*)d_out);
}

// round 4
// speedup vs baseline: 1.6249x; 1.6249x over previous
#include <cuda_runtime.h>
#include <cstdint>

#define NMAX 50000
#define EMAX 800000
#define RR 3
#define GGR 64

// ---------------- scratch (device globals; no allocation) ----------------
__device__ float g_xr   [RR*NMAX*64];
__device__ float g_beta [RR*NMAX*64];
__device__ float g_gamma[RR*NMAX*64];
__device__ float g_xs   [NMAX*64];
__device__ float g_fsb  [NMAX*64];
__device__ float g_fsg  [NMAX*64];
__device__ float g_xp   [NMAX*64];
__device__ float g_asrc [NMAX];
__device__ float g_adst [NMAX];
__device__ int      g_cnt[NMAX];
__device__ int      g_pos[NMAX];
__device__ int      g_off[NMAX+1];
__device__ unsigned g_rec[EMAX];
__device__ float g_feats[NMAX*128];
__device__ float g_pmax [GGR*128];
__device__ float g_pmean[GGR*128];
__device__ float g_hidden[GGR*64];

// ---------------- helpers ----------------
__device__ __forceinline__ uint64_t pack2(float a, float b){
    uint64_t r; asm("mov.b64 %0,{%1,%2};" : "=l"(r) : "f"(a), "f"(b)); return r;
}
__device__ __forceinline__ void fma2(uint64_t &d, uint64_t a, uint64_t b){
    asm("fma.rn.f32x2 %0,%1,%2,%0;" : "+l"(d) : "l"(a), "l"(b));
}

// ---------------- init: zero CSR counters ----------------
__global__ void kzero(int n){
    int i = blockIdx.x*blockDim.x + threadIdx.x;
    if (i < n){ g_cnt[i] = 0; g_pos[i] = 0; }
}

// ---------------- K1: fused node-dense GEMMs ----------------
__device__ __forceinline__ void tile64(
    const float* __restrict__ Wg, int ldw, int jof,
    const float* __restrict__ bias,
    float* __restrict__ outArr,
    float* Ws, const float* Xs, int tid, int node, int n)
{
    __syncthreads();
    #pragma unroll
    for (int k = tid; k < 4096; k += 128)
        Ws[k] = Wg[(k>>6)*ldw + jof + (k&63)];
    __syncthreads();

    uint64_t acc[32];
    if (bias){
        #pragma unroll
        for (int j = 0; j < 32; j++) acc[j] = pack2(bias[jof+2*j], bias[jof+2*j+1]);
    } else {
        #pragma unroll
        for (int j = 0; j < 32; j++) acc[j] = 0ull;
    }
    for (int d = 0; d < 64; d++){
        float xv = Xs[d*128 + tid];
        uint64_t x2 = pack2(xv, xv);
        const ulonglong2* wr = (const ulonglong2*)(Ws + d*64);
        #pragma unroll
        for (int j = 0; j < 16; j++){
            ulonglong2 w = wr[j];
            fma2(acc[2*j],   x2, w.x);
            fma2(acc[2*j+1], x2, w.y);
        }
    }
    if (node < n){
        ulonglong2* o = (ulonglong2*)(outArr + (size_t)node*64);
        #pragma unroll
        for (int j = 0; j < 16; j++) o[j] = make_ulonglong2(acc[2*j], acc[2*j+1]);
    }
}

__global__ __launch_bounds__(128) void k1(
    const float* __restrict__ x,
    const float* __restrict__ flW, const float* __restrict__ ffW, const float* __restrict__ ffb,
    const float* __restrict__ skW, const float* __restrict__ sfW, const float* __restrict__ sfb,
    const float* __restrict__ gatW, int n)
{
    extern __shared__ float sm[];
    float* Ws = sm;          // 4096 floats
    float* Xs = sm + 4096;   // 64*128 floats
    int tid = threadIdx.x;
    int node = blockIdx.x*128 + tid;
    int nc = node < n ? node : n-1;

    const float4* xr4 = (const float4*)(x + (size_t)nc*64);
    #pragma unroll
    for (int q = 0; q < 16; q++){
        float4 v = xr4[q];
        Xs[(4*q+0)*128 + tid] = v.x;
        Xs[(4*q+1)*128 + tid] = v.y;
        Xs[(4*q+2)*128 + tid] = v.z;
        Xs[(4*q+3)*128 + tid] = v.w;
    }

    tile64(skW, 64, 0,  (const float*)nullptr, g_xs,  Ws, Xs, tid, node, n);
    tile64(sfW, 128, 0,  sfb, g_fsb, Ws, Xs, tid, node, n);
    tile64(sfW, 128, 64, sfb, g_fsg, Ws, Xs, tid, node, n);
    for (int r = 0; r < RR; r++){
        tile64(flW + (size_t)r*64*64,  64, 0,  (const float*)nullptr,
               g_xr + (size_t)r*n*64, Ws, Xs, tid, node, n);
        tile64(ffW + (size_t)r*64*128, 128, 0,  ffb + r*128,
               g_beta + (size_t)r*n*64, Ws, Xs, tid, node, n);
        tile64(ffW + (size_t)r*64*128, 128, 64, ffb + r*128,
               g_gamma + (size_t)r*n*64, Ws, Xs, tid, node, n);
    }
    tile64(gatW, 64, 0, (const float*)nullptr, g_xp, Ws, Xs, tid, node, n);
}

// ---------------- K1b: attention scores ----------------
__global__ void k1b(const float* __restrict__ atS, const float* __restrict__ atD, int n){
    int w = (blockIdx.x*blockDim.x + threadIdx.x) >> 5;
    int lane = threadIdx.x & 31;
    if (w >= n) return;
    float2 v = ((const float2*)(g_xp + (size_t)w*64))[lane];
    float a = v.x*atS[2*lane] + v.y*atS[2*lane+1];
    float b = v.x*atD[2*lane] + v.y*atD[2*lane+1];
    #pragma unroll
    for (int o = 16; o; o >>= 1){
        a += __shfl_down_sync(0xffffffffu, a, o);
        b += __shfl_down_sync(0xffffffffu, b, o);
    }
    if (lane == 0){ g_asrc[w] = a; g_adst[w] = b; }
}

// ---------------- CSR build: histogram / scan / scatter ----------------
__global__ void khist(const int* __restrict__ dst, int E){
    int i = blockIdx.x*blockDim.x + threadIdx.x;
    if (i < E) atomicAdd(&g_cnt[dst[i]], 1);
}

__global__ void kscan(int n, int E){
    __shared__ int ss[1024];
    int t = threadIdx.x;
    int per = (n + 1023) / 1024;
    int b = t*per; int e = b + per; if (e > n) e = n; if (b > n) b = n;
    int s = 0;
    for (int i = b; i < e; i++) s += g_cnt[i];
    ss[t] = s; __syncthreads();
    for (int o = 1; o < 1024; o <<= 1){
        int u = (t >= o) ? ss[t-o] : 0;
        __syncthreads();
        ss[t] += u;
        __syncthreads();
    }
    int run = ss[t] - s;   // exclusive prefix
    for (int i = b; i < e; i++){ g_off[i] = run; run += g_cnt[i]; }
    if (t == 0) g_off[n] = E;
}

__global__ void kscatter(const int* __restrict__ src, const int* __restrict__ dst,
                         const int* __restrict__ et, int E){
    int i = blockIdx.x*blockDim.x + threadIdx.x;
    if (i >= E) return;
    int d = dst[i];
    int p = g_off[d] + atomicAdd(&g_pos[d], 1);
    g_rec[p] = (unsigned)src[i] | ((unsigned)et[i] << 20);
}

// ---------------- FiLM gather: warp per dst, no atomics ----------------
__global__ void kfilm(int n){
    int w = (blockIdx.x*blockDim.x + threadIdx.x) >> 5;
    int lane = threadIdx.x & 31;
    if (w >= n) return;
    int beg = g_off[w], end = g_off[w+1];

    // per-type gamma/beta rows at dst
    float2 gm0 = ((const float2*)(g_gamma + ((size_t)0*n + w)*64))[lane];
    float2 gm1 = ((const float2*)(g_gamma + ((size_t)1*n + w)*64))[lane];
    float2 gm2 = ((const float2*)(g_gamma + ((size_t)2*n + w)*64))[lane];
    float2 bt0 = ((const float2*)(g_beta  + ((size_t)0*n + w)*64))[lane];
    float2 bt1 = ((const float2*)(g_beta  + ((size_t)1*n + w)*64))[lane];
    float2 bt2 = ((const float2*)(g_beta  + ((size_t)2*n + w)*64))[lane];

    float2 a0 = make_float2(0.f,0.f), a1 = a0, a2 = a0;
    int c0 = 0, c1 = 0, c2 = 0;
    for (int e = beg; e < end; e++){
        unsigned rec = g_rec[e];
        int s = rec & 0xFFFFF;
        int t = rec >> 20;
        float2 xv = ((const float2*)(g_xr + ((size_t)t*n + s)*64))[lane];
        if (t == 0){
            a0.x += fmaxf(fmaf(gm0.x, xv.x, bt0.x), 0.f);
            a0.y += fmaxf(fmaf(gm0.y, xv.y, bt0.y), 0.f);
            c0++;
        } else if (t == 1){
            a1.x += fmaxf(fmaf(gm1.x, xv.x, bt1.x), 0.f);
            a1.y += fmaxf(fmaf(gm1.y, xv.y, bt1.y), 0.f);
            c1++;
        } else {
            a2.x += fmaxf(fmaf(gm2.x, xv.x, bt2.x), 0.f);
            a2.y += fmaxf(fmaf(gm2.y, xv.y, bt2.y), 0.f);
            c2++;
        }
    }
    float i0 = 1.f / (float)(c0 > 0 ? c0 : 1);
    float i1 = 1.f / (float)(c1 > 0 ? c1 : 1);
    float i2 = 1.f / (float)(c2 > 0 ? c2 : 1);
    float aggx = a0.x*i0 + a1.x*i1 + a2.x*i2;
    float aggy = a0.y*i0 + a1.y*i1 + a2.y*i2;

    // skip-FiLM finalize
    size_t o = (size_t)w*64 + lane*2;
    float2 xs = *(const float2*)(g_xs  + o);
    float2 fb = *(const float2*)(g_fsb + o);
    float2 fg = *(const float2*)(g_fsg + o);
    float o1x = fmaxf(fmaxf(fmaf(fg.x, xs.x, fb.x), 0.f) + aggx, 0.f);
    float o1y = fmaxf(fmaxf(fmaf(fg.y, xs.y, fb.y), 0.f) + aggy, 0.f);
    *(float2*)(g_feats + (size_t)w*128 + 2*lane) = make_float2(o1x, o1y);
}

// ---------------- GAT gather: warp per dst, online softmax ----------------
__global__ void kgat(const float* __restrict__ gatb, int n){
    int w = (blockIdx.x*blockDim.x + threadIdx.x) >> 5;
    int lane = threadIdx.x & 31;
    if (w >= n) return;
    int beg = g_off[w], end = g_off[w+1];

    float aD = g_adst[w];
    // self loop seeds the online softmax
    float ev = g_asrc[w] + aD;
    ev = ev < 0.f ? 0.2f*ev : ev;
    float m = ev, ssum = 1.f;
    float2 acc = ((const float2*)(g_xp + (size_t)w*64))[lane];

    for (int e = beg; e < end; e++){
        unsigned rec = g_rec[e];
        int s = rec & 0xFFFFF;
        float es = g_asrc[s] + aD;
        es = es < 0.f ? 0.2f*es : es;
        float al;
        if (es > m){
            float sc = __expf(m - es);
            acc.x *= sc; acc.y *= sc; ssum *= sc;
            m = es; al = 1.f;
        } else {
            al = __expf(es - m);
        }
        float2 xv = ((const float2*)(g_xp + (size_t)s*64))[lane];
        acc.x = fmaf(al, xv.x, acc.x);
        acc.y = fmaf(al, xv.y, acc.y);
        ssum += al;
    }
    float inv = 1.f / ssum;
    float o2x = fmaxf(fmaf(acc.x, inv, gatb[2*lane  ]), 0.f);
    float o2y = fmaxf(fmaf(acc.y, inv, gatb[2*lane+1]), 0.f);
    *(float2*)(g_feats + (size_t)w*128 + 64 + 2*lane) = make_float2(o2x, o2y);
}

// ---------------- pooling: block per graph, no atomics ----------------
__global__ void kpool(const int* __restrict__ gb, int n){
    int g = blockIdx.x, c = threadIdx.x; // 128 threads
    int lo = 0, hi = n;
    while (lo < hi){ int m = (lo+hi)>>1; if (gb[m] < g) lo = m+1; else hi = m; }
    int start = lo; hi = n;
    while (lo < hi){ int m = (lo+hi)>>1; if (gb[m] < g+1) lo = m+1; else hi = m; }
    int end = lo;
    float mx = 0.f, sm = 0.f;
    for (int i = start; i < end; i++){
        float v = g_feats[(size_t)i*128 + c];
        mx = fmaxf(mx, v); sm += v;
    }
    int cnt = end - start;
    g_pmax[g*128 + c]  = mx;
    g_pmean[g*128 + c] = sm / (float)(cnt > 0 ? cnt : 1);
}

// ---------------- MLP hidden ----------------
__global__ void k6a(const float* __restrict__ linW, const float* __restrict__ linb){
    int idx = blockIdx.x*blockDim.x + threadIdx.x;
    if (idx >= GGR*64) return;
    int g = idx >> 6, j = idx & 63;
    float s = linb[j];
    #pragma unroll 4
    for (int k = 0; k < 128; k++) s = fmaf(g_pmax[g*128 + k],  linW[k*64 + j], s);
    #pragma unroll 4
    for (int k = 0; k < 128; k++) s = fmaf(g_pmean[g*128 + k], linW[(128+k)*64 + j], s);
    g_hidden[idx] = fmaxf(s, 0.f);
}

// ---------------- logits + log_softmax ----------------
__global__ void k6b(const float* __restrict__ fcW, const float* __restrict__ fcb,
                    float* __restrict__ out){
    int g = threadIdx.x;
    if (g >= GGR) return;
    float l[10];
    #pragma unroll
    for (int c = 0; c < 10; c++) l[c] = fcb[c];
    for (int j = 0; j < 64; j++){
        float h = g_hidden[g*64 + j];
        #pragma unroll
        for (int c = 0; c < 10; c++) l[c] = fmaf(h, fcW[j*10 + c], l[c]);
    }
    float mx = l[0];
    #pragma unroll
    for (int c = 1; c < 10; c++) mx = fmaxf(mx, l[c]);
    float se = 0.f;
    #pragma unroll
    for (int c = 0; c < 10; c++) se += expf(l[c] - mx);
    float lse = mx + logf(se);
    #pragma unroll
    for (int c = 0; c < 10; c++) out[g*10 + c] = l[c] - lse;
}

// ---------------- launch ----------------
extern "C" void kernel_launch(void* const* d_in, const int* in_sizes, int n_in,
                              void* d_out, int out_size){
    const float* x    = (const float*)d_in[0];
    const int*   ei   = (const int*)  d_in[1];
    const int*   et   = (const int*)  d_in[2];
    const int*   gb   = (const int*)  d_in[3];
    const float* flW  = (const float*)d_in[4];
    const float* ffW  = (const float*)d_in[5];
    const float* ffb  = (const float*)d_in[6];
    const float* skW  = (const float*)d_in[7];
    const float* sfW  = (const float*)d_in[8];
    const float* sfb  = (const float*)d_in[9];
    const float* gatW = (const float*)d_in[10];
    const float* atS  = (const float*)d_in[11];
    const float* atD  = (const float*)d_in[12];
    const float* gatb = (const float*)d_in[13];
    const float* linW = (const float*)d_in[14];
    const float* linb = (const float*)d_in[15];
    const float* fcW  = (const float*)d_in[16];
    const float* fcb  = (const float*)d_in[17];

    int n = in_sizes[0] / 64;
    int E = in_sizes[1] / 2;
    const int* src = ei;
    const int* dst = ei + E;

    kzero<<<(n + 255)/256, 256>>>(n);
    k1<<<(n + 127)/128, 128, 49152>>>(x, flW, ffW, ffb, skW, sfW, sfb, gatW, n);
    k1b<<<(n + 7)/8, 256>>>(atS, atD, n);
    khist<<<(E + 255)/256, 256>>>(dst, E);
    kscan<<<1, 1024>>>(n, E);
    kscatter<<<(E + 255)/256, 256>>>(src, dst, et, E);
    kfilm<<<(n + 7)/8, 256>>>(n);
    kgat<<<(n + 7)/8, 256>>>(gatb, n);
    kpool<<<GGR, 128>>>(gb, n);
    k6a<<<(GGR*64 + 127)/128, 128>>>(linW, linb);
    k6b<<<1, 64>>>(fcW, fcb, (float*)d_out);
}

// round 6
// speedup vs baseline: 1.6932x; 1.0421x over previous
#include <cuda_runtime.h>
#include <cstdint>

#define NMAX 50000
#define EMAX 800000
#define RR 3
#define GGR 64
#define PCH 8

// ---------------- scratch (device globals; no allocation) ----------------
__device__ float g_xr   [RR*NMAX*64];
__device__ float g_beta [RR*NMAX*64];
__device__ float g_gamma[RR*NMAX*64];
__device__ float g_xs   [NMAX*64];
__device__ float g_fsb  [NMAX*64];
__device__ float g_fsg  [NMAX*64];
__device__ float g_xp   [NMAX*64];
__device__ float g_asrc [NMAX];
__device__ float g_adst [NMAX];
__device__ int      g_cnt[NMAX];
__device__ int      g_pos[NMAX];
__device__ int      g_off[NMAX+1];
__device__ unsigned g_rec[EMAX];
__device__ float g_feats[NMAX*128];
__device__ float g_ppmax[GGR*PCH*128];
__device__ float g_ppsum[GGR*PCH*128];
__device__ float g_pmax [GGR*128];
__device__ float g_pmean[GGR*128];
__device__ float g_hidden[GGR*64];

// ---------------- helpers ----------------
__device__ __forceinline__ uint64_t pack2(float a, float b){
    uint64_t r; asm("mov.b64 %0,{%1,%2};" : "=l"(r) : "f"(a), "f"(b)); return r;
}
__device__ __forceinline__ void fma2(uint64_t &d, uint64_t a, uint64_t b){
    asm("fma.rn.f32x2 %0,%1,%2,%0;" : "+l"(d) : "l"(a), "l"(b));
}

// ---------------- init: zero CSR counters ----------------
__global__ void kzero(int n){
    int i = blockIdx.x*blockDim.x + threadIdx.x;
    if (i < n){ g_cnt[i] = 0; g_pos[i] = 0; }
}

// ---------------- K1: fused node-dense GEMMs (+ attention dots) ----------------
__device__ __forceinline__ void tile64(
    const float* __restrict__ Wg, int ldw, int jof,
    const float* __restrict__ bias,
    float* __restrict__ outArr,
    float* Ws, const float* Xs, int tid, int node, int n,
    const float* __restrict__ atS, const float* __restrict__ atD)
{
    __syncthreads();
    #pragma unroll
    for (int k = tid; k < 4096; k += 128)
        Ws[k] = Wg[(k>>6)*ldw + jof + (k&63)];
    __syncthreads();

    uint64_t acc[32];
    if (bias){
        #pragma unroll
        for (int j = 0; j < 32; j++) acc[j] = pack2(bias[jof+2*j], bias[jof+2*j+1]);
    } else {
        #pragma unroll
        for (int j = 0; j < 32; j++) acc[j] = 0ull;
    }
    for (int d = 0; d < 64; d++){
        float xv = Xs[d*128 + tid];
        uint64_t x2 = pack2(xv, xv);
        const ulonglong2* wr = (const ulonglong2*)(Ws + d*64);
        #pragma unroll
        for (int j = 0; j < 16; j++){
            ulonglong2 w = wr[j];
            fma2(acc[2*j],   x2, w.x);
            fma2(acc[2*j+1], x2, w.y);
        }
    }
    if (node < n){
        ulonglong2* o = (ulonglong2*)(outArr + (size_t)node*64);
        #pragma unroll
        for (int j = 0; j < 16; j++) o[j] = make_ulonglong2(acc[2*j], acc[2*j+1]);
        if (atS){
            float a = 0.f, b = 0.f;
            #pragma unroll
            for (int j = 0; j < 32; j++){
                float lo = __uint_as_float((unsigned)acc[j]);
                float hi = __uint_as_float((unsigned)(acc[j] >> 32));
                a = fmaf(lo, __ldg(atS + 2*j), a); a = fmaf(hi, __ldg(atS + 2*j + 1), a);
                b = fmaf(lo, __ldg(atD + 2*j), b); b = fmaf(hi, __ldg(atD + 2*j + 1), b);
            }
            g_asrc[node] = a;
            g_adst[node] = b;
        }
    }
}

__global__ __launch_bounds__(128) void k1(
    const float* __restrict__ x,
    const float* __restrict__ flW, const float* __restrict__ ffW, const float* __restrict__ ffb,
    const float* __restrict__ skW, const float* __restrict__ sfW, const float* __restrict__ sfb,
    const float* __restrict__ gatW,
    const float* __restrict__ atS, const float* __restrict__ atD, int n)
{
    extern __shared__ float sm[];
    float* Ws = sm;          // 4096 floats
    float* Xs = sm + 4096;   // 64*128 floats
    int tid = threadIdx.x;
    int node = blockIdx.x*128 + tid;
    int nc = node < n ? node : n-1;

    const float4* xr4 = (const float4*)(x + (size_t)nc*64);
    #pragma unroll
    for (int q = 0; q < 16; q++){
        float4 v = xr4[q];
        Xs[(4*q+0)*128 + tid] = v.x;
        Xs[(4*q+1)*128 + tid] = v.y;
        Xs[(4*q+2)*128 + tid] = v.z;
        Xs[(4*q+3)*128 + tid] = v.w;
    }

    tile64(skW, 64, 0,  (const float*)nullptr, g_xs,  Ws, Xs, tid, node, n, nullptr, nullptr);
    tile64(sfW, 128, 0,  sfb, g_fsb, Ws, Xs, tid, node, n, nullptr, nullptr);
    tile64(sfW, 128, 64, sfb, g_fsg, Ws, Xs, tid, node, n, nullptr, nullptr);
    for (int r = 0; r < RR; r++){
        tile64(flW + (size_t)r*64*64,  64, 0,  (const float*)nullptr,
               g_xr + (size_t)r*n*64, Ws, Xs, tid, node, n, nullptr, nullptr);
        tile64(ffW + (size_t)r*64*128, 128, 0,  ffb + r*128,
               g_beta + (size_t)r*n*64, Ws, Xs, tid, node, n, nullptr, nullptr);
        tile64(ffW + (size_t)r*64*128, 128, 64, ffb + r*128,
               g_gamma + (size_t)r*n*64, Ws, Xs, tid, node, n, nullptr, nullptr);
    }
    tile64(gatW, 64, 0, (const float*)nullptr, g_xp, Ws, Xs, tid, node, n, atS, atD);
}

// ---------------- CSR build: histogram / scan / scatter ----------------
__global__ void khist(const int* __restrict__ dst, int E){
    int i = blockIdx.x*blockDim.x + threadIdx.x;
    if (i < E) atomicAdd(&g_cnt[dst[i]], 1);
}

__global__ void kscan(int n, int E){
    __shared__ int ss[1024];
    int t = threadIdx.x;
    int per = (n + 1023) / 1024;
    int b = t*per; int e = b + per; if (e > n) e = n; if (b > n) b = n;
    int s = 0;
    for (int i = b; i < e; i++) s += g_cnt[i];
    ss[t] = s; __syncthreads();
    for (int o = 1; o < 1024; o <<= 1){
        int u = (t >= o) ? ss[t-o] : 0;
        __syncthreads();
        ss[t] += u;
        __syncthreads();
    }
    int run = ss[t] - s;   // exclusive prefix
    for (int i = b; i < e; i++){ g_off[i] = run; run += g_cnt[i]; }
    if (t == 0) g_off[n] = E;
}

__global__ void kscatter(const int* __restrict__ src, const int* __restrict__ dst,
                         const int* __restrict__ et, int E){
    int i = blockIdx.x*blockDim.x + threadIdx.x;
    if (i >= E) return;
    int d = dst[i];
    int p = g_off[d] + atomicAdd(&g_pos[d], 1);
    g_rec[p] = (unsigned)src[i] | ((unsigned)et[i] << 20);
}

// ---------------- fused edge gather: FiLM + GAT, warp per dst ----------------
__global__ void kedge(const float* __restrict__ gatb, int n){
    int w = (blockIdx.x*blockDim.x + threadIdx.x) >> 5;
    int lane = threadIdx.x & 31;
    if (w >= n) return;
    int beg = g_off[w], end = g_off[w+1];

    // FiLM dst rows (gamma/beta per type)
    float2 gm0 = ((const float2*)(g_gamma + ((size_t)0*n + w)*64))[lane];
    float2 gm1 = ((const float2*)(g_gamma + ((size_t)1*n + w)*64))[lane];
    float2 gm2 = ((const float2*)(g_gamma + ((size_t)2*n + w)*64))[lane];
    float2 bt0 = ((const float2*)(g_beta  + ((size_t)0*n + w)*64))[lane];
    float2 bt1 = ((const float2*)(g_beta  + ((size_t)1*n + w)*64))[lane];
    float2 bt2 = ((const float2*)(g_beta  + ((size_t)2*n + w)*64))[lane];

    float2 a0 = make_float2(0.f,0.f), a1 = a0, a2 = a0;
    int c0 = 0, c1 = 0, c2 = 0;

    // GAT init: self loop seeds online softmax
    float aD = g_adst[w];
    float ev = g_asrc[w] + aD;
    ev = ev < 0.f ? 0.2f*ev : ev;
    float m = ev, ssum = 1.f;
    float2 gacc = ((const float2*)(g_xp + (size_t)w*64))[lane];

    for (int e = beg; e < end; e++){
        unsigned rec = g_rec[e];
        int s = rec & 0xFFFFF;
        int t = rec >> 20;

        // FiLM message
        float2 xv = ((const float2*)(g_xr + ((size_t)t*n + s)*64))[lane];
        if (t == 0){
            a0.x += fmaxf(fmaf(gm0.x, xv.x, bt0.x), 0.f);
            a0.y += fmaxf(fmaf(gm0.y, xv.y, bt0.y), 0.f);
            c0++;
        } else if (t == 1){
            a1.x += fmaxf(fmaf(gm1.x, xv.x, bt1.x), 0.f);
            a1.y += fmaxf(fmaf(gm1.y, xv.y, bt1.y), 0.f);
            c1++;
        } else {
            a2.x += fmaxf(fmaf(gm2.x, xv.x, bt2.x), 0.f);
            a2.y += fmaxf(fmaf(gm2.y, xv.y, bt2.y), 0.f);
            c2++;
        }

        // GAT message (online softmax)
        float es = g_asrc[s] + aD;
        es = es < 0.f ? 0.2f*es : es;
        float2 pv = ((const float2*)(g_xp + (size_t)s*64))[lane];
        float al;
        if (es > m){
            float sc = __expf(m - es);
            gacc.x *= sc; gacc.y *= sc; ssum *= sc;
            m = es; al = 1.f;
        } else {
            al = __expf(es - m);
        }
        gacc.x = fmaf(al, pv.x, gacc.x);
        gacc.y = fmaf(al, pv.y, gacc.y);
        ssum += al;
    }

    // FiLM finalize
    float i0 = 1.f / (float)(c0 > 0 ? c0 : 1);
    float i1 = 1.f / (float)(c1 > 0 ? c1 : 1);
    float i2 = 1.f / (float)(c2 > 0 ? c2 : 1);
    float aggx = a0.x*i0 + a1.x*i1 + a2.x*i2;
    float aggy = a0.y*i0 + a1.y*i1 + a2.y*i2;

    size_t o = (size_t)w*64 + lane*2;
    float2 xs = *(const float2*)(g_xs  + o);
    float2 fb = *(const float2*)(g_fsb + o);
    float2 fg = *(const float2*)(g_fsg + o);
    float o1x = fmaxf(fmaxf(fmaf(fg.x, xs.x, fb.x), 0.f) + aggx, 0.f);
    float o1y = fmaxf(fmaxf(fmaf(fg.y, xs.y, fb.y), 0.f) + aggy, 0.f);
    *(float2*)(g_feats + (size_t)w*128 + 2*lane) = make_float2(o1x, o1y);

    // GAT finalize
    float inv = 1.f / ssum;
    float o2x = fmaxf(fmaf(gacc.x, inv, gatb[2*lane  ]), 0.f);
    float o2y = fmaxf(fmaf(gacc.y, inv, gatb[2*lane+1]), 0.f);
    *(float2*)(g_feats + (size_t)w*128 + 64 + 2*lane) = make_float2(o2x, o2y);
}

// ---------------- pooling: (graph, chunk) partials, then reduce ----------------
__global__ void kpool(const int* __restrict__ gb, int n){
    int g = blockIdx.x / PCH, ch = blockIdx.x % PCH;
    int c = threadIdx.x; // 128
    int lo = 0, hi = n;
    while (lo < hi){ int m = (lo+hi)>>1; if (gb[m] < g) lo = m+1; else hi = m; }
    int start = lo; hi = n;
    while (lo < hi){ int m = (lo+hi)>>1; if (gb[m] < g+1) lo = m+1; else hi = m; }
    int end = lo;
    int len = end - start;
    int b = start + (len*ch)/PCH;
    int e = start + (len*(ch+1))/PCH;
    float mx = 0.f, sm = 0.f;
    for (int i = b; i < e; i++){
        float v = g_feats[(size_t)i*128 + c];
        mx = fmaxf(mx, v); sm += v;
    }
    g_ppmax[(g*PCH + ch)*128 + c] = mx;
    g_ppsum[(g*PCH + ch)*128 + c] = sm;
}

__global__ void kpoolred(const int* __restrict__ gb, int n){
    int g = blockIdx.x, c = threadIdx.x;
    int lo = 0, hi = n;
    while (lo < hi){ int m = (lo+hi)>>1; if (gb[m] < g) lo = m+1; else hi = m; }
    int start = lo; hi = n;
    while (lo < hi){ int m = (lo+hi)>>1; if (gb[m] < g+1) lo = m+1; else hi = m; }
    int cnt = lo - start;
    float mx = 0.f, sm = 0.f;
    #pragma unroll
    for (int ch = 0; ch < PCH; ch++){
        mx = fmaxf(mx, g_ppmax[(g*PCH + ch)*128 + c]);
        sm += g_ppsum[(g*PCH + ch)*128 + c];
    }
    g_pmax[g*128 + c]  = mx;
    g_pmean[g*128 + c] = sm / (float)(cnt > 0 ? cnt : 1);
}

// ---------------- MLP hidden ----------------
__global__ void k6a(const float* __restrict__ linW, const float* __restrict__ linb){
    int idx = blockIdx.x*blockDim.x + threadIdx.x;
    if (idx >= GGR*64) return;
    int g = idx >> 6, j = idx & 63;
    float s = linb[j];
    #pragma unroll 4
    for (int k = 0; k < 128; k++) s = fmaf(g_pmax[g*128 + k],  linW[k*64 + j], s);
    #pragma unroll 4
    for (int k = 0; k < 128; k++) s = fmaf(g_pmean[g*128 + k], linW[(128+k)*64 + j], s);
    g_hidden[idx] = fmaxf(s, 0.f);
}

// ---------------- logits + log_softmax ----------------
__global__ void k6b(const float* __restrict__ fcW, const float* __restrict__ fcb,
                    float* __restrict__ out){
    int g = threadIdx.x;
    if (g >= GGR) return;
    float l[10];
    #pragma unroll
    for (int c = 0; c < 10; c++) l[c] = fcb[c];
    for (int j = 0; j < 64; j++){
        float h = g_hidden[g*64 + j];
        #pragma unroll
        for (int c = 0; c < 10; c++) l[c] = fmaf(h, fcW[j*10 + c], l[c]);
    }
    float mx = l[0];
    #pragma unroll
    for (int c = 1; c < 10; c++) mx = fmaxf(mx, l[c]);
    float se = 0.f;
    #pragma unroll
    for (int c = 0; c < 10; c++) se += expf(l[c] - mx);
    float lse = mx + logf(se);
    #pragma unroll
    for (int c = 0; c < 10; c++) out[g*10 + c] = l[c] - lse;
}

// ---------------- launch ----------------
extern "C" void kernel_launch(void* const* d_in, const int* in_sizes, int n_in,
                              void* d_out, int out_size){
    const float* x    = (const float*)d_in[0];
    const int*   ei   = (const int*)  d_in[1];
    const int*   et   = (const int*)  d_in[2];
    const int*   gb   = (const int*)  d_in[3];
    const float* flW  = (const float*)d_in[4];
    const float* ffW  = (const float*)d_in[5];
    const float* ffb  = (const float*)d_in[6];
    const float* skW  = (const float*)d_in[7];
    const float* sfW  = (const float*)d_in[8];
    const float* sfb  = (const float*)d_in[9];
    const float* gatW = (const float*)d_in[10];
    const float* atS  = (const float*)d_in[11];
    const float* atD  = (const float*)d_in[12];
    const float* gatb = (const float*)d_in[13];
    const float* linW = (const float*)d_in[14];
    const float* linb = (const float*)d_in[15];
    const float* fcW  = (const float*)d_in[16];
    const float* fcb  = (const float*)d_in[17];

    int n = in_sizes[0] / 64;
    int E = in_sizes[1] / 2;
    const int* src = ei;
    const int* dst = ei + E;

    kzero<<<(n + 255)/256, 256>>>(n);
    k1<<<(n + 127)/128, 128, 49152>>>(x, flW, ffW, ffb, skW, sfW, sfb, gatW, atS, atD, n);
    khist<<<(E + 255)/256, 256>>>(dst, E);
    kscan<<<1, 1024>>>(n, E);
    kscatter<<<(E + 255)/256, 256>>>(src, dst, et, E);
    kedge<<<(n + 7)/8, 256>>>(gatb, n);
    kpool<<<GGR*PCH, 128>>>(gb, n);
    kpoolred<<<GGR, 128>>>(gb, n);
    k6a<<<(GGR*64 + 127)/128, 128>>>(linW, linb);
    k6b<<<1, 64>>>(fcW, fcb, (float*)d_out);
}

// round 7
// speedup vs baseline: 1.9756x; 1.1667x over previous
#include <cuda_runtime.h>
#include <cstdint>

#define NMAX 50000
#define EMAX 800000
#define RR 3
#define GGR 64
#define PCH 8
#define SCB 1024

// ---------------- scratch (device globals; no allocation) ----------------
__device__ float g_xr   [RR*NMAX*64];
__device__ float g_beta [RR*NMAX*64];
__device__ float g_gamma[RR*NMAX*64];
__device__ float g_xs   [NMAX*64];
__device__ float g_fsb  [NMAX*64];
__device__ float g_fsg  [NMAX*64];
__device__ float g_xp   [NMAX*64];
__device__ float g_asrc [NMAX];
__device__ float g_adst [NMAX];
__device__ int      g_cnt[NMAX];
__device__ int      g_pos[NMAX];
__device__ int      g_off[NMAX+1];
__device__ int      g_bsum[64];
__device__ int      g_bofs[64];
__device__ unsigned g_rec[EMAX];
__device__ float g_feats[NMAX*128];
__device__ float g_ppmax[GGR*PCH*128];
__device__ float g_ppsum[GGR*PCH*128];
__device__ float g_pmax [GGR*128];
__device__ float g_pmean[GGR*128];
__device__ float g_hidden[GGR*64];

// ---------------- helpers ----------------
__device__ __forceinline__ uint64_t pack2(float a, float b){
    uint64_t r; asm("mov.b64 %0,{%1,%2};" : "=l"(r) : "f"(a), "f"(b)); return r;
}
__device__ __forceinline__ void fma2(uint64_t &d, uint64_t a, uint64_t b){
    asm("fma.rn.f32x2 %0,%1,%2,%0;" : "+l"(d) : "l"(a), "l"(b));
}

// ---------------- init: zero CSR counters ----------------
__global__ void kzero(int n){
    int i = blockIdx.x*blockDim.x + threadIdx.x;
    if (i < n){ g_cnt[i] = 0; g_pos[i] = 0; }
}

// ---------------- K1: fused node-dense GEMMs (+ attention dots) ----------------
__device__ __forceinline__ void tile64(
    const float* __restrict__ Wg, int ldw, int jof,
    const float* __restrict__ bias,
    float* __restrict__ outArr,
    float* Ws, const float* Xs, int tid, int node, int n,
    const float* __restrict__ atS, const float* __restrict__ atD)
{
    __syncthreads();
    #pragma unroll
    for (int k = tid; k < 4096; k += 128)
        Ws[k] = Wg[(k>>6)*ldw + jof + (k&63)];
    __syncthreads();

    uint64_t acc[32];
    if (bias){
        #pragma unroll
        for (int j = 0; j < 32; j++) acc[j] = pack2(bias[jof+2*j], bias[jof+2*j+1]);
    } else {
        #pragma unroll
        for (int j = 0; j < 32; j++) acc[j] = 0ull;
    }
    for (int d = 0; d < 64; d++){
        float xv = Xs[d*128 + tid];
        uint64_t x2 = pack2(xv, xv);
        const ulonglong2* wr = (const ulonglong2*)(Ws + d*64);
        #pragma unroll
        for (int j = 0; j < 16; j++){
            ulonglong2 w = wr[j];
            fma2(acc[2*j],   x2, w.x);
            fma2(acc[2*j+1], x2, w.y);
        }
    }
    if (node < n){
        ulonglong2* o = (ulonglong2*)(outArr + (size_t)node*64);
        #pragma unroll
        for (int j = 0; j < 16; j++) o[j] = make_ulonglong2(acc[2*j], acc[2*j+1]);
        if (atS){
            float a = 0.f, b = 0.f;
            #pragma unroll
            for (int j = 0; j < 32; j++){
                float lo = __uint_as_float((unsigned)acc[j]);
                float hi = __uint_as_float((unsigned)(acc[j] >> 32));
                a = fmaf(lo, __ldg(atS + 2*j), a); a = fmaf(hi, __ldg(atS + 2*j + 1), a);
                b = fmaf(lo, __ldg(atD + 2*j), b); b = fmaf(hi, __ldg(atD + 2*j + 1), b);
            }
            g_asrc[node] = a;
            g_adst[node] = b;
        }
    }
}

__global__ __launch_bounds__(128) void k1(
    const float* __restrict__ x,
    const float* __restrict__ flW, const float* __restrict__ ffW, const float* __restrict__ ffb,
    const float* __restrict__ skW, const float* __restrict__ sfW, const float* __restrict__ sfb,
    const float* __restrict__ gatW,
    const float* __restrict__ atS, const float* __restrict__ atD, int n)
{
    extern __shared__ float sm[];
    float* Ws = sm;          // 4096 floats
    float* Xs = sm + 4096;   // 64*128 floats
    int tid = threadIdx.x;
    int node = blockIdx.x*128 + tid;
    int nc = node < n ? node : n-1;

    const float4* xr4 = (const float4*)(x + (size_t)nc*64);
    #pragma unroll
    for (int q = 0; q < 16; q++){
        float4 v = xr4[q];
        Xs[(4*q+0)*128 + tid] = v.x;
        Xs[(4*q+1)*128 + tid] = v.y;
        Xs[(4*q+2)*128 + tid] = v.z;
        Xs[(4*q+3)*128 + tid] = v.w;
    }

    tile64(skW, 64, 0,  (const float*)nullptr, g_xs,  Ws, Xs, tid, node, n, nullptr, nullptr);
    tile64(sfW, 128, 0,  sfb, g_fsb, Ws, Xs, tid, node, n, nullptr, nullptr);
    tile64(sfW, 128, 64, sfb, g_fsg, Ws, Xs, tid, node, n, nullptr, nullptr);
    for (int r = 0; r < RR; r++){
        tile64(flW + (size_t)r*64*64,  64, 0,  (const float*)nullptr,
               g_xr + (size_t)r*n*64, Ws, Xs, tid, node, n, nullptr, nullptr);
        tile64(ffW + (size_t)r*64*128, 128, 0,  ffb + r*128,
               g_beta + (size_t)r*n*64, Ws, Xs, tid, node, n, nullptr, nullptr);
        tile64(ffW + (size_t)r*64*128, 128, 64, ffb + r*128,
               g_gamma + (size_t)r*n*64, Ws, Xs, tid, node, n, nullptr, nullptr);
    }
    tile64(gatW, 64, 0, (const float*)nullptr, g_xp, Ws, Xs, tid, node, n, atS, atD);
}

// ---------------- CSR build: histogram / 3-phase scan / scatter ----------------
__global__ void khist(const int* __restrict__ dst, int E){
    int i = blockIdx.x*blockDim.x + threadIdx.x;
    if (i < E) atomicAdd(&g_cnt[dst[i]], 1);
}

__global__ __launch_bounds__(SCB) void kscanA(int n){
    __shared__ int wsum[32];
    int i = blockIdx.x*SCB + threadIdx.x;
    int lane = threadIdx.x & 31, wid = threadIdx.x >> 5;
    int v = (i < n) ? g_cnt[i] : 0;
    int inc = v;
    #pragma unroll
    for (int o = 1; o < 32; o <<= 1){
        int u = __shfl_up_sync(0xffffffffu, inc, o);
        if (lane >= o) inc += u;
    }
    if (lane == 31) wsum[wid] = inc;
    __syncthreads();
    if (wid == 0){
        int s = wsum[lane];
        int t = s;
        #pragma unroll
        for (int o = 1; o < 32; o <<= 1){
            int u = __shfl_up_sync(0xffffffffu, t, o);
            if (lane >= o) t += u;
        }
        wsum[lane] = t - s;   // exclusive warp offset
    }
    __syncthreads();
    int excl = inc - v + wsum[wid];
    if (i < n) g_off[i] = excl;
    if (threadIdx.x == SCB-1) g_bsum[blockIdx.x] = excl + v;
}

__global__ void kscanB(int nb){
    __shared__ int ss[64];
    int t = threadIdx.x;
    int v = (t < nb) ? g_bsum[t] : 0;
    ss[t] = v; __syncthreads();
    #pragma unroll
    for (int o = 1; o < 64; o <<= 1){
        int u = (t >= o) ? ss[t-o] : 0;
        __syncthreads();
        ss[t] += u;
        __syncthreads();
    }
    if (t < nb) g_bofs[t] = ss[t] - v;
}

__global__ __launch_bounds__(SCB) void kscanC(int n, int E){
    int i = blockIdx.x*SCB + threadIdx.x;
    if (i < n) g_off[i] += g_bofs[blockIdx.x];
    if (blockIdx.x == 0 && threadIdx.x == 0) g_off[n] = E;
}

__global__ void kscatter(const int* __restrict__ src, const int* __restrict__ dst,
                         const int* __restrict__ et, int E){
    int i = blockIdx.x*blockDim.x + threadIdx.x;
    if (i >= E) return;
    int d = dst[i];
    int p = g_off[d] + atomicAdd(&g_pos[d], 1);
    g_rec[p] = (unsigned)src[i] | ((unsigned)et[i] << 20);
}

// ---------------- fused edge gather: FiLM + GAT, warp per dst ----------------
__global__ void kedge(const float* __restrict__ gatb, int n){
    int w = (blockIdx.x*blockDim.x + threadIdx.x) >> 5;
    int lane = threadIdx.x & 31;
    if (w >= n) return;
    int beg = g_off[w], end = g_off[w+1];

    // FiLM dst rows (gamma/beta per type)
    float2 gm0 = ((const float2*)(g_gamma + ((size_t)0*n + w)*64))[lane];
    float2 gm1 = ((const float2*)(g_gamma + ((size_t)1*n + w)*64))[lane];
    float2 gm2 = ((const float2*)(g_gamma + ((size_t)2*n + w)*64))[lane];
    float2 bt0 = ((const float2*)(g_beta  + ((size_t)0*n + w)*64))[lane];
    float2 bt1 = ((const float2*)(g_beta  + ((size_t)1*n + w)*64))[lane];
    float2 bt2 = ((const float2*)(g_beta  + ((size_t)2*n + w)*64))[lane];

    float2 a0 = make_float2(0.f,0.f), a1 = a0, a2 = a0;
    int c0 = 0, c1 = 0, c2 = 0;

    // GAT init: self loop seeds online softmax
    float aD = g_adst[w];
    float ev = g_asrc[w] + aD;
    ev = ev < 0.f ? 0.2f*ev : ev;
    float m = ev, ssum = 1.f;
    float2 gacc = ((const float2*)(g_xp + (size_t)w*64))[lane];

    unsigned rec = (beg < end) ? g_rec[beg] : 0u;
    for (int e = beg; e < end; e++){
        // prefetch next record to break the serial rec->addr->load chain
        unsigned nrec = (e+1 < end) ? g_rec[e+1] : 0u;
        int s = rec & 0xFFFFF;
        int t = rec >> 20;

        // issue all independent gathers up front
        float2 xv = ((const float2*)(g_xr + ((size_t)t*n + s)*64))[lane];
        float2 pv = ((const float2*)(g_xp + (size_t)s*64))[lane];
        float as = g_asrc[s];

        // FiLM message
        if (t == 0){
            a0.x += fmaxf(fmaf(gm0.x, xv.x, bt0.x), 0.f);
            a0.y += fmaxf(fmaf(gm0.y, xv.y, bt0.y), 0.f);
            c0++;
        } else if (t == 1){
            a1.x += fmaxf(fmaf(gm1.x, xv.x, bt1.x), 0.f);
            a1.y += fmaxf(fmaf(gm1.y, xv.y, bt1.y), 0.f);
            c1++;
        } else {
            a2.x += fmaxf(fmaf(gm2.x, xv.x, bt2.x), 0.f);
            a2.y += fmaxf(fmaf(gm2.y, xv.y, bt2.y), 0.f);
            c2++;
        }

        // GAT message (online softmax)
        float es = as + aD;
        es = es < 0.f ? 0.2f*es : es;
        float al;
        if (es > m){
            float sc = __expf(m - es);
            gacc.x *= sc; gacc.y *= sc; ssum *= sc;
            m = es; al = 1.f;
        } else {
            al = __expf(es - m);
        }
        gacc.x = fmaf(al, pv.x, gacc.x);
        gacc.y = fmaf(al, pv.y, gacc.y);
        ssum += al;
        rec = nrec;
    }

    // FiLM finalize
    float i0 = 1.f / (float)(c0 > 0 ? c0 : 1);
    float i1 = 1.f / (float)(c1 > 0 ? c1 : 1);
    float i2 = 1.f / (float)(c2 > 0 ? c2 : 1);
    float aggx = a0.x*i0 + a1.x*i1 + a2.x*i2;
    float aggy = a0.y*i0 + a1.y*i1 + a2.y*i2;

    size_t o = (size_t)w*64 + lane*2;
    float2 xs = *(const float2*)(g_xs  + o);
    float2 fb = *(const float2*)(g_fsb + o);
    float2 fg = *(const float2*)(g_fsg + o);
    float o1x = fmaxf(fmaxf(fmaf(fg.x, xs.x, fb.x), 0.f) + aggx, 0.f);
    float o1y = fmaxf(fmaxf(fmaf(fg.y, xs.y, fb.y), 0.f) + aggy, 0.f);
    *(float2*)(g_feats + (size_t)w*128 + 2*lane) = make_float2(o1x, o1y);

    // GAT finalize
    float inv = 1.f / ssum;
    float o2x = fmaxf(fmaf(gacc.x, inv, gatb[2*lane  ]), 0.f);
    float o2y = fmaxf(fmaf(gacc.y, inv, gatb[2*lane+1]), 0.f);
    *(float2*)(g_feats + (size_t)w*128 + 64 + 2*lane) = make_float2(o2x, o2y);
}

// ---------------- pooling: (graph, chunk) partials, then reduce ----------------
__global__ void kpool(const int* __restrict__ gb, int n){
    int g = blockIdx.x / PCH, ch = blockIdx.x % PCH;
    int c = threadIdx.x; // 128
    int lo = 0, hi = n;
    while (lo < hi){ int m = (lo+hi)>>1; if (gb[m] < g) lo = m+1; else hi = m; }
    int start = lo; hi = n;
    while (lo < hi){ int m = (lo+hi)>>1; if (gb[m] < g+1) lo = m+1; else hi = m; }
    int end = lo;
    int len = end - start;
    int b = start + (len*ch)/PCH;
    int e = start + (len*(ch+1))/PCH;
    float mx = 0.f, sm = 0.f;
    for (int i = b; i < e; i++){
        float v = g_feats[(size_t)i*128 + c];
        mx = fmaxf(mx, v); sm += v;
    }
    g_ppmax[(g*PCH + ch)*128 + c] = mx;
    g_ppsum[(g*PCH + ch)*128 + c] = sm;
}

__global__ void kpoolred(const int* __restrict__ gb, int n){
    int g = blockIdx.x, c = threadIdx.x;
    int lo = 0, hi = n;
    while (lo < hi){ int m = (lo+hi)>>1; if (gb[m] < g) lo = m+1; else hi = m; }
    int start = lo; hi = n;
    while (lo < hi){ int m = (lo+hi)>>1; if (gb[m] < g+1) lo = m+1; else hi = m; }
    int cnt = lo - start;
    float mx = 0.f, sm = 0.f;
    #pragma unroll
    for (int ch = 0; ch < PCH; ch++){
        mx = fmaxf(mx, g_ppmax[(g*PCH + ch)*128 + c]);
        sm += g_ppsum[(g*PCH + ch)*128 + c];
    }
    g_pmax[g*128 + c]  = mx;
    g_pmean[g*128 + c] = sm / (float)(cnt > 0 ? cnt : 1);
}

// ---------------- MLP hidden ----------------
__global__ void k6a(const float* __restrict__ linW, const float* __restrict__ linb){
    int idx = blockIdx.x*blockDim.x + threadIdx.x;
    if (idx >= GGR*64) return;
    int g = idx >> 6, j = idx & 63;
    float s = linb[j];
    #pragma unroll 4
    for (int k = 0; k < 128; k++) s = fmaf(g_pmax[g*128 + k],  linW[k*64 + j], s);
    #pragma unroll 4
    for (int k = 0; k < 128; k++) s = fmaf(g_pmean[g*128 + k], linW[(128+k)*64 + j], s);
    g_hidden[idx] = fmaxf(s, 0.f);
}

// ---------------- logits + log_softmax ----------------
__global__ void k6b(const float* __restrict__ fcW, const float* __restrict__ fcb,
                    float* __restrict__ out){
    int g = threadIdx.x;
    if (g >= GGR) return;
    float l[10];
    #pragma unroll
    for (int c = 0; c < 10; c++) l[c] = fcb[c];
    for (int j = 0; j < 64; j++){
        float h = g_hidden[g*64 + j];
        #pragma unroll
        for (int c = 0; c < 10; c++) l[c] = fmaf(h, fcW[j*10 + c], l[c]);
    }
    float mx = l[0];
    #pragma unroll
    for (int c = 1; c < 10; c++) mx = fmaxf(mx, l[c]);
    float se = 0.f;
    #pragma unroll
    for (int c = 0; c < 10; c++) se += expf(l[c] - mx);
    float lse = mx + logf(se);
    #pragma unroll
    for (int c = 0; c < 10; c++) out[g*10 + c] = l[c] - lse;
}

// ---------------- launch ----------------
extern "C" void kernel_launch(void* const* d_in, const int* in_sizes, int n_in,
                              void* d_out, int out_size){
    const float* x    = (const float*)d_in[0];
    const int*   ei   = (const int*)  d_in[1];
    const int*   et   = (const int*)  d_in[2];
    const int*   gb   = (const int*)  d_in[3];
    const float* flW  = (const float*)d_in[4];
    const float* ffW  = (const float*)d_in[5];
    const float* ffb  = (const float*)d_in[6];
    const float* skW  = (const float*)d_in[7];
    const float* sfW  = (const float*)d_in[8];
    const float* sfb  = (const float*)d_in[9];
    const float* gatW = (const float*)d_in[10];
    const float* atS  = (const float*)d_in[11];
    const float* atD  = (const float*)d_in[12];
    const float* gatb = (const float*)d_in[13];
    const float* linW = (const float*)d_in[14];
    const float* linb = (const float*)d_in[15];
    const float* fcW  = (const float*)d_in[16];
    const float* fcb  = (const float*)d_in[17];

    int n = in_sizes[0] / 64;
    int E = in_sizes[1] / 2;
    const int* src = ei;
    const int* dst = ei + E;

    // lazy one-time stream/event setup (first call is the non-captured
    // correctness run, so creation never happens inside graph capture)
    static cudaStream_t s2 = nullptr;
    static cudaEvent_t evFork = nullptr, evJoin = nullptr;
    if (!s2){
        cudaStreamCreateWithFlags(&s2, cudaStreamNonBlocking);
        cudaEventCreateWithFlags(&evFork, cudaEventDisableTiming);
        cudaEventCreateWithFlags(&evJoin, cudaEventDisableTiming);
    }

    int nbScan = (n + SCB-1)/SCB;

    // fork: CSR build on side stream, dense GEMMs on main stream
    cudaEventRecord(evFork, 0);
    cudaStreamWaitEvent(s2, evFork, 0);

    kzero   <<<(n + 255)/256, 256, 0, s2>>>(n);
    khist   <<<(E + 255)/256, 256, 0, s2>>>(dst, E);
    kscanA  <<<nbScan, SCB, 0, s2>>>(n);
    kscanB  <<<1, 64, 0, s2>>>(nbScan);
    kscanC  <<<nbScan, SCB, 0, s2>>>(n, E);
    kscatter<<<(E + 255)/256, 256, 0, s2>>>(src, dst, et, E);
    cudaEventRecord(evJoin, s2);

    k1<<<(n + 127)/128, 128, 49152>>>(x, flW, ffW, ffb, skW, sfW, sfb, gatW, atS, atD, n);

    // join: kedge needs both k1 outputs and the CSR
    cudaStreamWaitEvent(0, evJoin, 0);
    kedge<<<(n + 7)/8, 256>>>(gatb, n);
    kpool<<<GGR*PCH, 128>>>(gb, n);
    kpoolred<<<GGR, 128>>>(gb, n);
    k6a<<<(GGR*64 + 127)/128, 128>>>(linW, linb);
    k6b<<<1, 64>>>(fcW, fcb, (float*)d_out);
}

// round 8
// speedup vs baseline: 2.1569x; 1.0918x over previous
#include <cuda_runtime.h>
#include <cstdint>

#define NMAX 50000
#define EMAX 800000
#define RR 3
#define GGR 64
#define PCH 8
#define SCB 1024

// ---------------- scratch (device globals; no allocation) ----------------
__device__ float g_xr   [RR*NMAX*64];
__device__ float g_beta [RR*NMAX*64];
__device__ float g_gamma[RR*NMAX*64];
__device__ float g_xs   [NMAX*64];
__device__ float g_fsb  [NMAX*64];
__device__ float g_fsg  [NMAX*64];
__device__ float g_xp   [NMAX*64];
__device__ float g_asrc [NMAX];
__device__ float g_adst [NMAX];
__device__ int      g_cnt[RR*NMAX];
__device__ int      g_pos[RR*NMAX];
__device__ int      g_off[RR*NMAX+1];
__device__ int      g_bsum[256];
__device__ int      g_bofs[256];
__device__ int      g_rec[EMAX];
__device__ float g_feats[NMAX*128];
__device__ float g_ppmax[GGR*PCH*128];
__device__ float g_ppsum[GGR*PCH*128];
__device__ float g_pmax [GGR*128];
__device__ float g_pmean[GGR*128];
__device__ float g_hidden[GGR*64];

// ---------------- helpers ----------------
__device__ __forceinline__ uint64_t pack2(float a, float b){
    uint64_t r; asm("mov.b64 %0,{%1,%2};" : "=l"(r) : "f"(a), "f"(b)); return r;
}
__device__ __forceinline__ void fma2(uint64_t &d, uint64_t a, uint64_t b){
    asm("fma.rn.f32x2 %0,%1,%2,%0;" : "+l"(d) : "l"(a), "l"(b));
}

// ---------------- init: zero CSR counters ----------------
__global__ void kzero(int m){
    int i = blockIdx.x*blockDim.x + threadIdx.x;
    if (i < m){ g_cnt[i] = 0; g_pos[i] = 0; }
}

// ---------------- K1: fused node-dense GEMMs (+ attention dots) ----------------
__device__ __forceinline__ void tile64(
    const float* __restrict__ Wg, int ldw, int jof,
    const float* __restrict__ bias,
    float* __restrict__ outArr,
    float* Ws, const float* Xs, int tid, int node, int n,
    const float* __restrict__ atS, const float* __restrict__ atD)
{
    __syncthreads();
    #pragma unroll
    for (int k = tid; k < 4096; k += 128)
        Ws[k] = Wg[(k>>6)*ldw + jof + (k&63)];
    __syncthreads();

    uint64_t acc[32];
    if (bias){
        #pragma unroll
        for (int j = 0; j < 32; j++) acc[j] = pack2(bias[jof+2*j], bias[jof+2*j+1]);
    } else {
        #pragma unroll
        for (int j = 0; j < 32; j++) acc[j] = 0ull;
    }
    for (int d = 0; d < 64; d++){
        float xv = Xs[d*128 + tid];
        uint64_t x2 = pack2(xv, xv);
        const ulonglong2* wr = (const ulonglong2*)(Ws + d*64);
        #pragma unroll
        for (int j = 0; j < 16; j++){
            ulonglong2 w = wr[j];
            fma2(acc[2*j],   x2, w.x);
            fma2(acc[2*j+1], x2, w.y);
        }
    }
    if (node < n){
        ulonglong2* o = (ulonglong2*)(outArr + (size_t)node*64);
        #pragma unroll
        for (int j = 0; j < 16; j++) o[j] = make_ulonglong2(acc[2*j], acc[2*j+1]);
        if (atS){
            float a = 0.f, b = 0.f;
            #pragma unroll
            for (int j = 0; j < 32; j++){
                float lo = __uint_as_float((unsigned)acc[j]);
                float hi = __uint_as_float((unsigned)(acc[j] >> 32));
                a = fmaf(lo, __ldg(atS + 2*j), a); a = fmaf(hi, __ldg(atS + 2*j + 1), a);
                b = fmaf(lo, __ldg(atD + 2*j), b); b = fmaf(hi, __ldg(atD + 2*j + 1), b);
            }
            g_asrc[node] = a;
            g_adst[node] = b;
        }
    }
}

__global__ __launch_bounds__(128) void k1(
    const float* __restrict__ x,
    const float* __restrict__ flW, const float* __restrict__ ffW, const float* __restrict__ ffb,
    const float* __restrict__ skW, const float* __restrict__ sfW, const float* __restrict__ sfb,
    const float* __restrict__ gatW,
    const float* __restrict__ atS, const float* __restrict__ atD, int n)
{
    extern __shared__ float sm[];
    float* Ws = sm;          // 4096 floats
    float* Xs = sm + 4096;   // 64*128 floats
    int tid = threadIdx.x;
    int node = blockIdx.x*128 + tid;
    int nc = node < n ? node : n-1;

    const float4* xr4 = (const float4*)(x + (size_t)nc*64);
    #pragma unroll
    for (int q = 0; q < 16; q++){
        float4 v = xr4[q];
        Xs[(4*q+0)*128 + tid] = v.x;
        Xs[(4*q+1)*128 + tid] = v.y;
        Xs[(4*q+2)*128 + tid] = v.z;
        Xs[(4*q+3)*128 + tid] = v.w;
    }

    tile64(skW, 64, 0,  (const float*)nullptr, g_xs,  Ws, Xs, tid, node, n, nullptr, nullptr);
    tile64(sfW, 128, 0,  sfb, g_fsb, Ws, Xs, tid, node, n, nullptr, nullptr);
    tile64(sfW, 128, 64, sfb, g_fsg, Ws, Xs, tid, node, n, nullptr, nullptr);
    for (int r = 0; r < RR; r++){
        tile64(flW + (size_t)r*64*64,  64, 0,  (const float*)nullptr,
               g_xr + (size_t)r*n*64, Ws, Xs, tid, node, n, nullptr, nullptr);
        tile64(ffW + (size_t)r*64*128, 128, 0,  ffb + r*128,
               g_beta + (size_t)r*n*64, Ws, Xs, tid, node, n, nullptr, nullptr);
        tile64(ffW + (size_t)r*64*128, 128, 64, ffb + r*128,
               g_gamma + (size_t)r*n*64, Ws, Xs, tid, node, n, nullptr, nullptr);
    }
    tile64(gatW, 64, 0, (const float*)nullptr, g_xp, Ws, Xs, tid, node, n, atS, atD);
}

// ---------------- CSR build over (dst*3 + type) keys ----------------
__global__ void khist(const int* __restrict__ dst, const int* __restrict__ et, int E){
    int i = blockIdx.x*blockDim.x + threadIdx.x;
    if (i < E) atomicAdd(&g_cnt[dst[i]*RR + et[i]], 1);
}

__global__ __launch_bounds__(SCB) void kscanA(int m){
    __shared__ int wsum[32];
    int i = blockIdx.x*SCB + threadIdx.x;
    int lane = threadIdx.x & 31, wid = threadIdx.x >> 5;
    int v = (i < m) ? g_cnt[i] : 0;
    int inc = v;
    #pragma unroll
    for (int o = 1; o < 32; o <<= 1){
        int u = __shfl_up_sync(0xffffffffu, inc, o);
        if (lane >= o) inc += u;
    }
    if (lane == 31) wsum[wid] = inc;
    __syncthreads();
    if (wid == 0){
        int s = wsum[lane];
        int t = s;
        #pragma unroll
        for (int o = 1; o < 32; o <<= 1){
            int u = __shfl_up_sync(0xffffffffu, t, o);
            if (lane >= o) t += u;
        }
        wsum[lane] = t - s;   // exclusive warp offset
    }
    __syncthreads();
    int excl = inc - v + wsum[wid];
    if (i < m) g_off[i] = excl;
    if (threadIdx.x == SCB-1) g_bsum[blockIdx.x] = excl + v;
}

__global__ void kscanB(int nb){
    __shared__ int ss[256];
    int t = threadIdx.x;
    int v = (t < nb) ? g_bsum[t] : 0;
    ss[t] = v; __syncthreads();
    #pragma unroll
    for (int o = 1; o < 256; o <<= 1){
        int u = (t >= o) ? ss[t-o] : 0;
        __syncthreads();
        ss[t] += u;
        __syncthreads();
    }
    if (t < nb) g_bofs[t] = ss[t] - v;
}

__global__ __launch_bounds__(SCB) void kscanC(int m, int E){
    int i = blockIdx.x*SCB + threadIdx.x;
    if (i < m) g_off[i] += g_bofs[blockIdx.x];
    if (blockIdx.x == 0 && threadIdx.x == 0) g_off[m] = E;
}

__global__ void kscatter(const int* __restrict__ src, const int* __restrict__ dst,
                         const int* __restrict__ et, int E){
    int i = blockIdx.x*blockDim.x + threadIdx.x;
    if (i >= E) return;
    int key = dst[i]*RR + et[i];
    int p = g_off[key] + atomicAdd(&g_pos[key], 1);
    g_rec[p] = src[i];
}

// ---------------- fused edge gather: FiLM + GAT, warp per dst ----------------
__global__ void kedge(const float* __restrict__ gatb, int n){
    int w = (blockIdx.x*blockDim.x + threadIdx.x) >> 5;
    int lane = threadIdx.x & 31;
    if (w >= n) return;

    // GAT seed (self loop); no max-shift needed: |e| is tiny, exp safe
    float aD = g_adst[w];
    float es0 = g_asrc[w] + aD;
    float ssum = __expf(fmaxf(es0, 0.2f*es0));
    float2 xpw = ((const float2*)(g_xp + (size_t)w*64))[lane];
    float2 gacc = make_float2(ssum*xpw.x, ssum*xpw.y);

    float aggx = 0.f, aggy = 0.f;
    int base = w*RR;
    #pragma unroll
    for (int t = 0; t < RR; t++){
        int beg = g_off[base+t], end = g_off[base+t+1];
        if (beg == end) continue;
        const float* xrb = g_xr + (size_t)t*n*64;
        float2 gm = ((const float2*)(g_gamma + ((size_t)t*n + w)*64))[lane];
        float2 bt = ((const float2*)(g_beta  + ((size_t)t*n + w)*64))[lane];
        float ax = 0.f, ay = 0.f;
        int s = g_rec[beg];
        for (int e = beg; e < end; e++){
            int sn = (e+1 < end) ? g_rec[e+1] : 0;
            // independent gathers up front
            float2 xv = ((const float2*)(xrb  + (size_t)s*64))[lane];
            float2 pv = ((const float2*)(g_xp + (size_t)s*64))[lane];
            float as = g_asrc[s];
            // FiLM
            ax += fmaxf(fmaf(gm.x, xv.x, bt.x), 0.f);
            ay += fmaxf(fmaf(gm.y, xv.y, bt.y), 0.f);
            // GAT
            float es = as + aD;
            float al = __expf(fmaxf(es, 0.2f*es));
            gacc.x = fmaf(al, pv.x, gacc.x);
            gacc.y = fmaf(al, pv.y, gacc.y);
            ssum += al;
            s = sn;
        }
        float inv = 1.f / (float)(end - beg);
        aggx = fmaf(ax, inv, aggx);
        aggy = fmaf(ay, inv, aggy);
    }

    // FiLM finalize
    size_t o = (size_t)w*64 + lane*2;
    float2 xs = *(const float2*)(g_xs  + o);
    float2 fb = *(const float2*)(g_fsb + o);
    float2 fg = *(const float2*)(g_fsg + o);
    float o1x = fmaxf(fmaxf(fmaf(fg.x, xs.x, fb.x), 0.f) + aggx, 0.f);
    float o1y = fmaxf(fmaxf(fmaf(fg.y, xs.y, fb.y), 0.f) + aggy, 0.f);
    *(float2*)(g_feats + (size_t)w*128 + 2*lane) = make_float2(o1x, o1y);

    // GAT finalize
    float inv = 1.f / ssum;
    float o2x = fmaxf(fmaf(gacc.x, inv, gatb[2*lane  ]), 0.f);
    float o2y = fmaxf(fmaf(gacc.y, inv, gatb[2*lane+1]), 0.f);
    *(float2*)(g_feats + (size_t)w*128 + 64 + 2*lane) = make_float2(o2x, o2y);
}

// ---------------- pooling: (graph, chunk) partials, then reduce ----------------
__global__ void kpool(const int* __restrict__ gb, int n){
    int g = blockIdx.x / PCH, ch = blockIdx.x % PCH;
    int c = threadIdx.x; // 128
    int lo = 0, hi = n;
    while (lo < hi){ int m = (lo+hi)>>1; if (gb[m] < g) lo = m+1; else hi = m; }
    int start = lo; hi = n;
    while (lo < hi){ int m = (lo+hi)>>1; if (gb[m] < g+1) lo = m+1; else hi = m; }
    int end = lo;
    int len = end - start;
    int b = start + (len*ch)/PCH;
    int e = start + (len*(ch+1))/PCH;
    float mx = 0.f, sm = 0.f;
    for (int i = b; i < e; i++){
        float v = g_feats[(size_t)i*128 + c];
        mx = fmaxf(mx, v); sm += v;
    }
    g_ppmax[(g*PCH + ch)*128 + c] = mx;
    g_ppsum[(g*PCH + ch)*128 + c] = sm;
}

__global__ void kpoolred(const int* __restrict__ gb, int n){
    int g = blockIdx.x, c = threadIdx.x;
    int lo = 0, hi = n;
    while (lo < hi){ int m = (lo+hi)>>1; if (gb[m] < g) lo = m+1; else hi = m; }
    int start = lo; hi = n;
    while (lo < hi){ int m = (lo+hi)>>1; if (gb[m] < g+1) lo = m+1; else hi = m; }
    int cnt = lo - start;
    float mx = 0.f, sm = 0.f;
    #pragma unroll
    for (int ch = 0; ch < PCH; ch++){
        mx = fmaxf(mx, g_ppmax[(g*PCH + ch)*128 + c]);
        sm += g_ppsum[(g*PCH + ch)*128 + c];
    }
    g_pmax[g*128 + c]  = mx;
    g_pmean[g*128 + c] = sm / (float)(cnt > 0 ? cnt : 1);
}

// ---------------- MLP hidden ----------------
__global__ void k6a(const float* __restrict__ linW, const float* __restrict__ linb){
    int idx = blockIdx.x*blockDim.x + threadIdx.x;
    if (idx >= GGR*64) return;
    int g = idx >> 6, j = idx & 63;
    float s = linb[j];
    #pragma unroll 4
    for (int k = 0; k < 128; k++) s = fmaf(g_pmax[g*128 + k],  linW[k*64 + j], s);
    #pragma unroll 4
    for (int k = 0; k < 128; k++) s = fmaf(g_pmean[g*128 + k], linW[(128+k)*64 + j], s);
    g_hidden[idx] = fmaxf(s, 0.f);
}

// ---------------- logits + log_softmax ----------------
__global__ void k6b(const float* __restrict__ fcW, const float* __restrict__ fcb,
                    float* __restrict__ out){
    int g = threadIdx.x;
    if (g >= GGR) return;
    float l[10];
    #pragma unroll
    for (int c = 0; c < 10; c++) l[c] = fcb[c];
    for (int j = 0; j < 64; j++){
        float h = g_hidden[g*64 + j];
        #pragma unroll
        for (int c = 0; c < 10; c++) l[c] = fmaf(h, fcW[j*10 + c], l[c]);
    }
    float mx = l[0];
    #pragma unroll
    for (int c = 1; c < 10; c++) mx = fmaxf(mx, l[c]);
    float se = 0.f;
    #pragma unroll
    for (int c = 0; c < 10; c++) se += expf(l[c] - mx);
    float lse = mx + logf(se);
    #pragma unroll
    for (int c = 0; c < 10; c++) out[g*10 + c] = l[c] - lse;
}

// ---------------- launch ----------------
extern "C" void kernel_launch(void* const* d_in, const int* in_sizes, int n_in,
                              void* d_out, int out_size){
    const float* x    = (const float*)d_in[0];
    const int*   ei   = (const int*)  d_in[1];
    const int*   et   = (const int*)  d_in[2];
    const int*   gb   = (const int*)  d_in[3];
    const float* flW  = (const float*)d_in[4];
    const float* ffW  = (const float*)d_in[5];
    const float* ffb  = (const float*)d_in[6];
    const float* skW  = (const float*)d_in[7];
    const float* sfW  = (const float*)d_in[8];
    const float* sfb  = (const float*)d_in[9];
    const float* gatW = (const float*)d_in[10];
    const float* atS  = (const float*)d_in[11];
    const float* atD  = (const float*)d_in[12];
    const float* gatb = (const float*)d_in[13];
    const float* linW = (const float*)d_in[14];
    const float* linb = (const float*)d_in[15];
    const float* fcW  = (const float*)d_in[16];
    const float* fcb  = (const float*)d_in[17];

    int n = in_sizes[0] / 64;
    int E = in_sizes[1] / 2;
    const int* src = ei;
    const int* dst = ei + E;
    int m = n * RR;

    static cudaStream_t s2 = nullptr;
    static cudaEvent_t evFork = nullptr, evJoin = nullptr;
    if (!s2){
        cudaStreamCreateWithFlags(&s2, cudaStreamNonBlocking);
        cudaEventCreateWithFlags(&evFork, cudaEventDisableTiming);
        cudaEventCreateWithFlags(&evJoin, cudaEventDisableTiming);
    }

    int nbScan = (m + SCB-1)/SCB;

    // fork: CSR build on side stream, dense GEMMs on main stream
    // (k1 is deliberately the 4th enqueued kernel so ncu's fixed-index
    //  capture lands on it next round)
    cudaEventRecord(evFork, 0);
    cudaStreamWaitEvent(s2, evFork, 0);

    kzero   <<<(m + 255)/256, 256, 0, s2>>>(m);
    khist   <<<(E + 255)/256, 256, 0, s2>>>(dst, et, E);
    kscanA  <<<nbScan, SCB, 0, s2>>>(m);

    k1<<<(n + 127)/128, 128, 49152>>>(x, flW, ffW, ffb, skW, sfW, sfb, gatW, atS, atD, n);

    kscanB  <<<1, 256, 0, s2>>>(nbScan);
    kscanC  <<<nbScan, SCB, 0, s2>>>(m, E);
    kscatter<<<(E + 255)/256, 256, 0, s2>>>(src, dst, et, E);
    cudaEventRecord(evJoin, s2);

    // join: kedge needs both k1 outputs and the CSR
    cudaStreamWaitEvent(0, evJoin, 0);
    kedge<<<(n + 7)/8, 256>>>(gatb, n);
    kpool<<<GGR*PCH, 128>>>(gb, n);
    kpoolred<<<GGR, 128>>>(gb, n);
    k6a<<<(GGR*64 + 127)/128, 128>>>(linW, linb);
    k6b<<<1, 64>>>(fcW, fcb, (float*)d_out);
}